// round 3
// baseline (speedup 1.0000x reference)
#include <cuda_runtime.h>
#include <cuda_bf16.h>
#include <math.h>

// Problem constants
#define TT 65536
#define BB 64
#define XX 512
#define YY 2560
#define HH 512

// -------- scratch (device globals; no allocation allowed) --------
__device__ float g_c[BB * HH];                 // per-batch folded bias (io_embed @ W1b + b1)
__device__ float g_H1[(size_t)TT * HH];        // layer-1 activations
__device__ float g_H2[(size_t)TT * HH];        // layer-2 activations
__device__ float g_logits[TT];
__device__ float g_pooled[BB * XX];

// ====================================================================
// K1: c[b][h] = sum_y io_embed[b][y] * W1[512+y][h] + b1[h]
// ====================================================================
__global__ void k_compute_c(const float* __restrict__ io,
                            const float* __restrict__ W1,
                            const float* __restrict__ b1) {
    int b = blockIdx.x;
    int h = threadIdx.x;                 // 512 threads
    const float* e = io + b * YY;
    const float* w = W1 + (size_t)XX * HH + h;   // rows 512..3071
    float acc = b1[h];
#pragma unroll 4
    for (int y = 0; y < YY; y++)
        acc = fmaf(e[y], w[(size_t)y * HH], acc);
    g_c[b * HH + h] = acc;
}

// ====================================================================
// K2/K3: C = relu(A @ W + bias),  M x 512 x 512 GEMM
//   mode row-bias: bias row = g_c[seg[m]]   (layer 1)
//   mode col-bias: bias = colbias[n]        (layer 2)
// Block tile 128x128, BK=16, 256 threads, 8x8 microtile.
// ====================================================================
__global__ __launch_bounds__(256, 2)
void k_mlp_gemm(const float* __restrict__ A,
                const float* __restrict__ W,
                const float* __restrict__ colbias,   // null for layer1
                const int*   __restrict__ seg,       // null for layer2
                float* __restrict__ C) {
    __shared__ float As[16][132];    // transposed, padded (2-way STS conflict max)
    __shared__ float Bs[16][128];

    const int tid = threadIdx.x;
    const int tx  = tid & 15;
    const int ty  = tid >> 4;
    const int col0 = blockIdx.x * 128;
    const int row0 = blockIdx.y * 128;

    float acc[8][8];
#pragma unroll
    for (int i = 0; i < 8; i++)
#pragma unroll
        for (int j = 0; j < 8; j++) acc[i][j] = 0.f;

    for (int k0 = 0; k0 < 512; k0 += 16) {
        // load A tile (128 x 16) -> As[k][m] (transposed)
#pragma unroll
        for (int it = 0; it < 2; it++) {
            int idx = tid + it * 256;          // 0..511 float4s
            int r = idx >> 2, c4 = idx & 3;
            float4 v = *(const float4*)(A + (size_t)(row0 + r) * 512 + k0 + c4 * 4);
            As[c4 * 4 + 0][r] = v.x;
            As[c4 * 4 + 1][r] = v.y;
            As[c4 * 4 + 2][r] = v.z;
            As[c4 * 4 + 3][r] = v.w;
        }
        // load B tile (16 x 128)
#pragma unroll
        for (int it = 0; it < 2; it++) {
            int idx = tid + it * 256;
            int r = idx >> 5, c4 = idx & 31;
            *(float4*)&Bs[r][c4 * 4] =
                *(const float4*)(W + (size_t)(k0 + r) * 512 + col0 + c4 * 4);
        }
        __syncthreads();

#pragma unroll
        for (int k = 0; k < 16; k++) {
            float a[8], b[8];
            *(float4*)(a)     = *(const float4*)&As[k][ty * 4];
            *(float4*)(a + 4) = *(const float4*)&As[k][64 + ty * 4];
            *(float4*)(b)     = *(const float4*)&Bs[k][tx * 4];
            *(float4*)(b + 4) = *(const float4*)&Bs[k][64 + tx * 4];
#pragma unroll
            for (int i = 0; i < 8; i++)
#pragma unroll
                for (int j = 0; j < 8; j++)
                    acc[i][j] = fmaf(a[i], b[j], acc[i][j]);
        }
        __syncthreads();
    }

    // epilogue: bias + relu + store
#pragma unroll
    for (int i = 0; i < 8; i++) {
        int r = row0 + ((i < 4) ? (ty * 4 + i) : (64 + ty * 4 + i - 4));
        const float* brow = nullptr;
        if (seg) brow = g_c + (size_t)seg[r] * HH;
#pragma unroll
        for (int jj = 0; jj < 2; jj++) {
            int c = col0 + ((jj == 0) ? (tx * 4) : (64 + tx * 4));
            float4 bv;
            if (seg) bv = *(const float4*)(brow + c);
            else     bv = *(const float4*)(colbias + c);
            float4 v;
            v.x = fmaxf(acc[i][jj * 4 + 0] + bv.x, 0.f);
            v.y = fmaxf(acc[i][jj * 4 + 1] + bv.y, 0.f);
            v.z = fmaxf(acc[i][jj * 4 + 2] + bv.z, 0.f);
            v.w = fmaxf(acc[i][jj * 4 + 3] + bv.w, 0.f);
            *(float4*)(C + (size_t)r * 512 + c) = v;
        }
    }
}

// ====================================================================
// K4: logits[t] = H2[t] . W3 + b3   (one warp per token)
// ====================================================================
__global__ void k_logits(const float* __restrict__ W3,
                         const float* __restrict__ b3) {
    int gw   = (blockIdx.x * blockDim.x + threadIdx.x) >> 5;
    int lane = threadIdx.x & 31;
    if (gw >= TT) return;
    const float* row = g_H2 + (size_t)gw * HH;
    float acc = 0.f;
#pragma unroll 4
    for (int k = lane; k < HH; k += 32)
        acc = fmaf(row[k], W3[k], acc);
#pragma unroll
    for (int o = 16; o > 0; o >>= 1)
        acc += __shfl_down_sync(0xffffffffu, acc, o);
    if (lane == 0) g_logits[gw] = acc + b3[0];
}

// ====================================================================
// K5: per-segment softmax + weighted pooling.  One block per segment.
// ====================================================================
__global__ void k_seg_pool(const int* __restrict__ seg,
                           const float* __restrict__ ps) {
    __shared__ float sbuf[512];
    __shared__ float s_mx, s_denom;
    const int b   = blockIdx.x;
    const int tid = threadIdx.x;

    // binary search ragged bounds (segment_ids sorted)
    int lo = 0, hi = TT;
    while (lo < hi) { int mid = (lo + hi) >> 1; if (seg[mid] < b) lo = mid + 1; else hi = mid; }
    const int start = lo;
    lo = start; hi = TT;
    while (lo < hi) { int mid = (lo + hi) >> 1; if (seg[mid] < b + 1) lo = mid + 1; else hi = mid; }
    const int end = lo;

    // pass 1: max
    float m = -1e30f;
    for (int t = start + tid; t < end; t += 512) m = fmaxf(m, g_logits[t]);
    sbuf[tid] = m; __syncthreads();
    for (int s = 256; s > 0; s >>= 1) {
        if (tid < s) sbuf[tid] = fmaxf(sbuf[tid], sbuf[tid + s]);
        __syncthreads();
    }
    if (tid == 0) s_mx = sbuf[0];
    __syncthreads();
    const float mx = s_mx;

    // pass 2: denom
    float sm = 0.f;
    for (int t = start + tid; t < end; t += 512) sm += expf(g_logits[t] - mx);
    __syncthreads();
    sbuf[tid] = sm; __syncthreads();
    for (int s = 256; s > 0; s >>= 1) {
        if (tid < s) sbuf[tid] += sbuf[tid + s];
        __syncthreads();
    }
    if (tid == 0) s_denom = sbuf[0];
    __syncthreads();
    const float inv = (end > start) ? 1.f / s_denom : 0.f;

    // pass 3: pooled[b][x] = sum_t e_t * ps[t][x] / denom   (x = tid)
    float acc = 0.f;
    for (int c0 = start; c0 < end; c0 += 512) {
        int nt = min(512, end - c0);
        __syncthreads();
        if (tid < nt) sbuf[tid] = expf(g_logits[c0 + tid] - mx);
        __syncthreads();
        for (int i = 0; i < nt; i++)
            acc = fmaf(sbuf[i], ps[(size_t)(c0 + i) * XX + tid], acc);
    }
    g_pooled[b * XX + tid] = acc * inv;
}

// ====================================================================
// K6: out[b] = relu(pooled[b] @ Wf1 + bf1) @ Wf2 + bf2
// ====================================================================
__global__ void k_final(const float* __restrict__ Wf1,
                        const float* __restrict__ bf1,
                        const float* __restrict__ Wf2,
                        const float* __restrict__ bf2,
                        float* __restrict__ out) {
    __shared__ float p[512];
    __shared__ float hf[512];
    const int b = blockIdx.x;
    const int tid = threadIdx.x;

    p[tid] = g_pooled[b * XX + tid];
    __syncthreads();

    float acc = bf1[tid];
#pragma unroll 4
    for (int k = 0; k < 512; k++)
        acc = fmaf(p[k], Wf1[(size_t)k * 512 + tid], acc);
    hf[tid] = fmaxf(acc, 0.f);
    __syncthreads();

    float v0 = hf[tid] * Wf2[tid * 2 + 0];
    float v1 = hf[tid] * Wf2[tid * 2 + 1];
    __syncthreads();
    p[tid] = v0; __syncthreads();
    for (int s = 256; s > 0; s >>= 1) { if (tid < s) p[tid] += p[tid + s]; __syncthreads(); }
    if (tid == 0) out[b * 2 + 0] = p[0] + bf2[0];
    __syncthreads();
    p[tid] = v1; __syncthreads();
    for (int s = 256; s > 0; s >>= 1) { if (tid < s) p[tid] += p[tid + s]; __syncthreads(); }
    if (tid == 0) out[b * 2 + 1] = p[0] + bf2[1];
}

// ====================================================================
extern "C" void kernel_launch(void* const* d_in, const int* in_sizes, int n_in,
                              void* d_out, int out_size) {
    const float* ps   = (const float*)d_in[0];   // (T, X)
    const float* io   = (const float*)d_in[1];   // (B, K, X) -> (B, Y)
    const int*   seg  = (const int*)  d_in[2];   // (T,)
    const float* W1   = (const float*)d_in[3];   // (X+Y, H)
    const float* b1   = (const float*)d_in[4];
    const float* W2   = (const float*)d_in[5];   // (H, H)
    const float* b2   = (const float*)d_in[6];
    const float* W3   = (const float*)d_in[7];   // (H, 1)
    const float* b3   = (const float*)d_in[8];
    const float* Wf1  = (const float*)d_in[9];   // (H, H)
    const float* bf1  = (const float*)d_in[10];
    const float* Wf2  = (const float*)d_in[11];  // (H, 2)
    const float* bf2  = (const float*)d_in[12];
    float* out = (float*)d_out;                  // (B, 2)

    float* H1; cudaGetSymbolAddress((void**)&H1, g_H1);
    float* H2; cudaGetSymbolAddress((void**)&H2, g_H2);

    // 1. fold io_embed @ W1[512:] + b1 into per-batch bias c
    k_compute_c<<<BB, 512>>>(io, W1, b1);

    // 2. H1 = relu(ps @ W1[:512] + c[seg])
    k_mlp_gemm<<<dim3(4, TT / 128), 256>>>(ps, W1, nullptr, seg, H1);

    // 3. H2 = relu(H1 @ W2 + b2)
    k_mlp_gemm<<<dim3(4, TT / 128), 256>>>(H1, W2, b2, nullptr, H2);

    // 4. logits
    k_logits<<<(TT * 32) / 256, 256>>>(W3, b3);

    // 5. segment softmax + pooling
    k_seg_pool<<<BB, 512>>>(seg, ps);

    // 6. final head
    k_final<<<BB, 512>>>(Wf1, bf1, Wf2, bf2, out);
}

// round 8
// speedup vs baseline: 1.7808x; 1.7808x over previous
#include <cuda_runtime.h>
#include <math.h>
#include <stdint.h>

#define TT 65536
#define BB 64
#define XX 512
#define HH 512
#define YY 2560

// -------- scratch (device globals; no allocation allowed) --------
__device__ float g_c[BB * HH];
__device__ float g_H1[(size_t)TT * HH];
__device__ float g_part[(size_t)4 * TT];   // per-n-block logit partials
__device__ float g_logits[TT];
__device__ float g_pooled[BB * XX];

__device__ __forceinline__ float rna_tf32(float x) {
    float r; asm("cvt.rna.tf32.f32 %0, %1;" : "=f"(r) : "f"(x)); return r;
}

#define MMA_TF32(d, a, b) \
    asm volatile("mma.sync.aligned.m16n8k8.row.col.f32.tf32.tf32.f32 " \
        "{%0,%1,%2,%3}, {%4,%5,%6,%7}, {%8,%9}, {%0,%1,%2,%3};" \
        : "+f"((d)[0]), "+f"((d)[1]), "+f"((d)[2]), "+f"((d)[3]) \
        : "r"((a)[0]), "r"((a)[1]), "r"((a)[2]), "r"((a)[3]), \
          "r"((b)[0]), "r"((b)[1]))

// ====================================================================
// K1: c[b][h] = sum_y io_embed[b][y] * W1[512+y][h] + b1[h]  (exact fp32)
// ====================================================================
__global__ void k_compute_c(const float* __restrict__ io,
                            const float* __restrict__ W1,
                            const float* __restrict__ b1) {
    int b = blockIdx.x;
    int h = threadIdx.x;                          // 512 threads
    const float* e = io + b * YY;
    const float* w = W1 + (size_t)XX * HH + h;    // rows 512..3071
    float acc = b1[h];
#pragma unroll 4
    for (int y = 0; y < YY; y++)
        acc = fmaf(e[y], w[(size_t)y * HH], acc);
    g_c[b * HH + h] = acc;
}

// ====================================================================
// tf32 mma.sync GEMM: D(128x128 per CTA) = A(Tx512) @ W(512x512), K=512.
// Block 128x128x16, 256 threads = 8 warps, warp tile 64x32 (m16n8k8).
// MODE 0: Out=H1, epilogue relu(D + c[seg[row]]), tf32-rounded.
// MODE 1: per-row partial logit sum_n relu(D+b2[n])*W3[n] -> g_part.
// Register-staged double buffering; operands RNA-rounded to tf32 at STS.
// ====================================================================
template <int MODE>
__global__ __launch_bounds__(256, 2)
void k_gemm_mma(const float* __restrict__ A,     // T x 512 row-major
               const float* __restrict__ W,      // 512 x 512 row-major (k,n)
               const int*   __restrict__ seg,    // MODE 0
               const float* __restrict__ b2,     // MODE 1
               const float* __restrict__ W3,     // MODE 1
               float* __restrict__ Out) {
    __shared__ float As[2][16][136];   // [k][m], pad->stride%32==8: conflict-free frags
    __shared__ float Bs[2][16][136];   // [k][n]
    __shared__ float s_red[4][128];    // MODE 1 cross-warp logit reduce
    __shared__ float s_b2[128], s_w3[128];

    const int tid  = threadIdx.x;
    const int wid  = tid >> 5, lane = tid & 31;
    const int g    = lane >> 2, tg = lane & 3;
    const int wm   = (wid & 1) * 64;      // warp m offset
    const int wn   = (wid >> 1) * 32;     // warp n offset
    const int row0 = blockIdx.y * 128, col0 = blockIdx.x * 128;

    if (MODE == 1 && tid < 128) {
        s_b2[tid] = b2[col0 + tid];
        s_w3[tid] = W3[col0 + tid];
    }

    float acc[4][4][4];
#pragma unroll
    for (int mi = 0; mi < 4; mi++)
#pragma unroll
        for (int ni = 0; ni < 4; ni++)
#pragma unroll
            for (int q = 0; q < 4; q++) acc[mi][ni][q] = 0.f;

    // load helpers: A tile 128x16 (512 f4), B tile 16x128 (512 f4); 2 f4/thread
    float4 pa[2], pb[2];
#define LDG_TILES(kt) do { \
    _Pragma("unroll") \
    for (int i = 0; i < 2; i++) { \
        int idx = tid + i * 256; \
        int ar = idx >> 2, ac4 = idx & 3; \
        pa[i] = *(const float4*)(A + (size_t)(row0 + ar) * 512 + (kt) * 16 + ac4 * 4); \
        int br = idx >> 5, bc = idx & 31; \
        pb[i] = *(const float4*)(W + (size_t)((kt) * 16 + br) * 512 + col0 + bc * 4); \
    } } while (0)
#define STS_TILES(buf) do { \
    _Pragma("unroll") \
    for (int i = 0; i < 2; i++) { \
        int idx = tid + i * 256; \
        int ar = idx >> 2, ac4 = idx & 3; \
        As[buf][ac4 * 4 + 0][ar] = rna_tf32(pa[i].x); \
        As[buf][ac4 * 4 + 1][ar] = rna_tf32(pa[i].y); \
        As[buf][ac4 * 4 + 2][ar] = rna_tf32(pa[i].z); \
        As[buf][ac4 * 4 + 3][ar] = rna_tf32(pa[i].w); \
        int br = idx >> 5, bc = idx & 31; \
        float4 v; \
        v.x = rna_tf32(pb[i].x); v.y = rna_tf32(pb[i].y); \
        v.z = rna_tf32(pb[i].z); v.w = rna_tf32(pb[i].w); \
        *(float4*)&Bs[buf][br][bc * 4] = v; \
    } } while (0)

    LDG_TILES(0);
    STS_TILES(0);
    __syncthreads();

    for (int kt = 0; kt < 32; kt++) {
        const int buf = kt & 1;
        if (kt < 31) LDG_TILES(kt + 1);

#pragma unroll
        for (int ks = 0; ks < 2; ks++) {
            const int k0 = ks * 8;
            uint32_t af[4][4], bf[4][2];
#pragma unroll
            for (int mi = 0; mi < 4; mi++) {
                int m = wm + mi * 16 + g;
                af[mi][0] = __float_as_uint(As[buf][k0 + tg][m]);
                af[mi][1] = __float_as_uint(As[buf][k0 + tg][m + 8]);
                af[mi][2] = __float_as_uint(As[buf][k0 + tg + 4][m]);
                af[mi][3] = __float_as_uint(As[buf][k0 + tg + 4][m + 8]);
            }
#pragma unroll
            for (int ni = 0; ni < 4; ni++) {
                int n = wn + ni * 8 + g;
                bf[ni][0] = __float_as_uint(Bs[buf][k0 + tg][n]);
                bf[ni][1] = __float_as_uint(Bs[buf][k0 + tg + 4][n]);
            }
#pragma unroll
            for (int mi = 0; mi < 4; mi++)
#pragma unroll
                for (int ni = 0; ni < 4; ni++)
                    MMA_TF32(acc[mi][ni], af[mi], bf[ni]);
        }

        if (kt < 31) {
            STS_TILES(buf ^ 1);
            __syncthreads();
        }
    }

    // -------- epilogue --------
    // c frag (m16n8): c0 (g, 2tg), c1 (g, 2tg+1), c2 (g+8, 2tg), c3 (g+8, 2tg+1)
    if (MODE == 0) {
#pragma unroll
        for (int mi = 0; mi < 4; mi++) {
#pragma unroll
            for (int h = 0; h < 2; h++) {
                int r = row0 + wm + mi * 16 + g + h * 8;
                const float* crow = g_c + (size_t)__ldg(seg + r) * 512;
                float* orow = Out + (size_t)r * 512;
#pragma unroll
                for (int ni = 0; ni < 4; ni++) {
                    int col = col0 + wn + ni * 8 + 2 * tg;
                    float2 cc = *(const float2*)(crow + col);
                    float2 o;
                    o.x = rna_tf32(fmaxf(acc[mi][ni][h * 2 + 0] + cc.x, 0.f));
                    o.y = rna_tf32(fmaxf(acc[mi][ni][h * 2 + 1] + cc.y, 0.f));
                    *(float2*)(orow + col) = o;
                }
            }
        }
    } else {
        // per-row partial logit over this CTA's 128 columns
        float rp[4][2];
#pragma unroll
        for (int mi = 0; mi < 4; mi++) {
#pragma unroll
            for (int h = 0; h < 2; h++) {
                float s = 0.f;
#pragma unroll
                for (int ni = 0; ni < 4; ni++) {
                    int cl = wn + ni * 8 + 2 * tg;   // local col
                    s = fmaf(fmaxf(acc[mi][ni][h * 2 + 0] + s_b2[cl], 0.f), s_w3[cl], s);
                    s = fmaf(fmaxf(acc[mi][ni][h * 2 + 1] + s_b2[cl + 1], 0.f), s_w3[cl + 1], s);
                }
                // reduce over tg (lanes g*4 + tg are consecutive)
                s += __shfl_xor_sync(0xffffffffu, s, 1);
                s += __shfl_xor_sync(0xffffffffu, s, 2);
                rp[mi][h] = s;
            }
        }
        __syncthreads();   // tiles done; reuse smem phase boundary
        if (tg == 0) {
#pragma unroll
            for (int mi = 0; mi < 4; mi++)
#pragma unroll
                for (int h = 0; h < 2; h++)
                    s_red[wid >> 1][wm + mi * 16 + g + h * 8] = rp[mi][h];
        }
        __syncthreads();
        if (tid < 128) {
            float v = s_red[0][tid] + s_red[1][tid] + s_red[2][tid] + s_red[3][tid];
            g_part[(size_t)blockIdx.x * TT + row0 + tid] = v;
        }
    }
#undef LDG_TILES
#undef STS_TILES
}

// ====================================================================
// logits[t] = sum of 4 n-block partials + b3   (deterministic reduce)
// ====================================================================
__global__ void k_logit_red(const float* __restrict__ b3) {
    int t = blockIdx.x * 256 + threadIdx.x;
    g_logits[t] = g_part[t] + g_part[TT + t] + g_part[2 * (size_t)TT + t]
                + g_part[3 * (size_t)TT + t] + b3[0];
}

// ====================================================================
// K5: per-segment softmax + weighted pooling.  Grid (B, 4), 128 threads.
// ====================================================================
__global__ void k_seg_pool(const int* __restrict__ seg,
                           const float* __restrict__ ps) {
    __shared__ float sbuf[128];
    __shared__ float s_mx, s_dn;
    const int b   = blockIdx.x;
    const int tid = threadIdx.x;

    int lo = 0, hi = TT;
    while (lo < hi) { int mid = (lo + hi) >> 1; if (seg[mid] < b) lo = mid + 1; else hi = mid; }
    const int start = lo;
    hi = TT;
    while (lo < hi) { int mid = (lo + hi) >> 1; if (seg[mid] < b + 1) lo = mid + 1; else hi = mid; }
    const int end = lo;

    float m = -1e30f;
    for (int t = start + tid; t < end; t += 128) m = fmaxf(m, g_logits[t]);
    sbuf[tid] = m; __syncthreads();
    for (int s = 64; s > 0; s >>= 1) {
        if (tid < s) sbuf[tid] = fmaxf(sbuf[tid], sbuf[tid + s]);
        __syncthreads();
    }
    if (tid == 0) s_mx = sbuf[0];
    __syncthreads();
    const float mx = s_mx;

    float sm = 0.f;
    for (int t = start + tid; t < end; t += 128) sm += expf(g_logits[t] - mx);
    __syncthreads();
    sbuf[tid] = sm; __syncthreads();
    for (int s = 64; s > 0; s >>= 1) {
        if (tid < s) sbuf[tid] += sbuf[tid + s];
        __syncthreads();
    }
    if (tid == 0) s_dn = sbuf[0];
    __syncthreads();
    const float inv = (end > start) ? 1.f / s_dn : 0.f;

    const int col = blockIdx.y * 128 + tid;
    float acc = 0.f;
    for (int c0 = start; c0 < end; c0 += 128) {
        int nt = min(128, end - c0);
        __syncthreads();
        if (tid < nt) sbuf[tid] = expf(g_logits[c0 + tid] - mx);
        __syncthreads();
        for (int i = 0; i < nt; i++)
            acc = fmaf(sbuf[i], ps[(size_t)(c0 + i) * XX + col], acc);
    }
    g_pooled[(size_t)b * XX + col] = acc * inv;
}

// ====================================================================
// K6: out[b] = relu(pooled[b] @ Wf1 + bf1) @ Wf2 + bf2   (exact fp32)
// ====================================================================
__global__ void k_final(const float* __restrict__ Wf1,
                        const float* __restrict__ bf1,
                        const float* __restrict__ Wf2,
                        const float* __restrict__ bf2,
                        float* __restrict__ out) {
    __shared__ float p[512];
    __shared__ float hf[512];
    const int b = blockIdx.x;
    const int tid = threadIdx.x;

    p[tid] = g_pooled[b * XX + tid];
    __syncthreads();

    float acc = bf1[tid];
#pragma unroll 4
    for (int k = 0; k < 512; k++)
        acc = fmaf(p[k], Wf1[(size_t)k * 512 + tid], acc);
    hf[tid] = fmaxf(acc, 0.f);
    __syncthreads();

    float v0 = hf[tid] * Wf2[tid * 2 + 0];
    float v1 = hf[tid] * Wf2[tid * 2 + 1];
    __syncthreads();
    p[tid] = v0; __syncthreads();
    for (int s = 256; s > 0; s >>= 1) { if (tid < s) p[tid] += p[tid + s]; __syncthreads(); }
    if (tid == 0) out[b * 2 + 0] = p[0] + bf2[0];
    __syncthreads();
    p[tid] = v1; __syncthreads();
    for (int s = 256; s > 0; s >>= 1) { if (tid < s) p[tid] += p[tid + s]; __syncthreads(); }
    if (tid == 0) out[b * 2 + 1] = p[0] + bf2[1];
}

// ====================================================================
extern "C" void kernel_launch(void* const* d_in, const int* in_sizes, int n_in,
                              void* d_out, int out_size) {
    const float* ps  = (const float*)d_in[0];
    const float* io  = (const float*)d_in[1];
    const int*   seg = (const int*)  d_in[2];
    const float* W1  = (const float*)d_in[3];
    const float* b1  = (const float*)d_in[4];
    const float* W2  = (const float*)d_in[5];
    const float* b2  = (const float*)d_in[6];
    const float* W3  = (const float*)d_in[7];
    const float* b3  = (const float*)d_in[8];
    const float* Wf1 = (const float*)d_in[9];
    const float* bf1 = (const float*)d_in[10];
    const float* Wf2 = (const float*)d_in[11];
    const float* bf2 = (const float*)d_in[12];
    float* out = (float*)d_out;

    float* H1; cudaGetSymbolAddress((void**)&H1, g_H1);

    // 1. fold io_embed @ W1[512:] + b1 into per-batch bias c
    k_compute_c<<<BB, 512>>>(io, W1, b1);

    // 2. H1 = relu(ps @ W1[:512] + c[seg])  — tf32 mma.sync
    k_gemm_mma<0><<<dim3(4, TT / 128), 256>>>(ps, W1, seg, nullptr, nullptr, H1);

    // 3. logit partials = relu(H1 @ W2 + b2) . W3 per n-block — fused, H2 never stored
    k_gemm_mma<1><<<dim3(4, TT / 128), 256>>>(H1, W2, nullptr, b2, W3, nullptr);

    // 4. logits = sum partials + b3
    k_logit_red<<<TT / 256, 256>>>(b3);

    // 5. segment softmax + pooling
    k_seg_pool<<<dim3(BB, 4), 128>>>(seg, ps);

    // 6. final head
    k_final<<<BB, 512>>>(Wf1, bf1, Wf2, bf2, out);
}

// round 10
// speedup vs baseline: 2.1932x; 1.2316x over previous
#include <cuda_runtime.h>
#include <cuda_bf16.h>
#include <math.h>
#include <stdint.h>

#define TT 65536
#define BB 64
#define XX 512
#define HH 512
#define YY 2560

// -------- scratch (device globals; no allocation allowed) --------
__device__ float g_c[BB * HH];
__device__ __nv_bfloat16 g_H1b[(size_t)TT * HH];
__device__ __nv_bfloat16 g_WT1b[HH * HH];   // W1[:512] transposed [n][k], bf16
__device__ __nv_bfloat16 g_WT2b[HH * HH];   // W2 transposed [n][k], bf16
__device__ float g_part[2 * TT];
__device__ float g_logits[TT];
__device__ float g_pooled[BB * XX];

// ==================== PTX helpers ====================
__device__ __forceinline__ uint32_t smem_u32(const void* p) {
    uint32_t a;
    asm("{ .reg .u64 t; cvta.to.shared.u64 t, %1; cvt.u32.u64 %0, t; }"
        : "=r"(a) : "l"(p));
    return a;
}
#define CP16(dst, src) \
    asm volatile("cp.async.cg.shared.global [%0], [%1], 16;" :: "r"(dst), "l"(src))
#define CPCOMMIT() asm volatile("cp.async.commit_group;" ::: "memory")
#define CPWAIT0()  asm volatile("cp.async.wait_group 0;" ::: "memory")

#define LDSM4(r, addr) \
    asm volatile("ldmatrix.sync.aligned.m8n8.x4.shared.b16 {%0,%1,%2,%3}, [%4];" \
        : "=r"((r)[0]), "=r"((r)[1]), "=r"((r)[2]), "=r"((r)[3]) : "r"(addr))

#define MMA_BF16(d, a, b) \
    asm volatile("mma.sync.aligned.m16n8k16.row.col.f32.bf16.bf16.f32 " \
        "{%0,%1,%2,%3}, {%4,%5,%6,%7}, {%8,%9}, {%0,%1,%2,%3};" \
        : "+f"((d)[0]), "+f"((d)[1]), "+f"((d)[2]), "+f"((d)[3]) \
        : "r"((a)[0]), "r"((a)[1]), "r"((a)[2]), "r"((a)[3]), \
          "r"((b)[0]), "r"((b)[1]))

// ====================================================================
// K0: WT[n][k] = bf16(W[k][n])   (512x512 transpose + convert)
// ====================================================================
__global__ void k_wt(const float* __restrict__ W, __nv_bfloat16* __restrict__ WT) {
    __shared__ float t[32][33];
    int bx = blockIdx.x * 32, by = blockIdx.y * 32;
    int x = threadIdx.x, y = threadIdx.y;         // (32, 8)
#pragma unroll
    for (int i = 0; i < 32; i += 8)
        t[y + i][x] = W[(size_t)(by + y + i) * HH + bx + x];
    __syncthreads();
#pragma unroll
    for (int i = 0; i < 32; i += 8)
        WT[(size_t)(bx + y + i) * HH + by + x] = __float2bfloat16(t[x][y + i]);
}

// ====================================================================
// K1: c[b][h] = sum_y io_embed[b][y] * W1[512+y][h] + b1[h]  (exact fp32)
// ====================================================================
__global__ void k_compute_c(const float* __restrict__ io,
                            const float* __restrict__ W1,
                            const float* __restrict__ b1) {
    int b = blockIdx.x;
    int h = threadIdx.x;                          // 512 threads
    const float* e = io + b * YY;
    const float* w = W1 + (size_t)XX * HH + h;
    float acc = b1[h];
#pragma unroll 4
    for (int y = 0; y < YY; y++)
        acc = fmaf(e[y], w[(size_t)y * HH], acc);
    g_c[b * HH + h] = acc;
}

// ====================================================================
// bf16 mma.sync GEMM: block 128(M)x256(N), BK=32, 256 thr = 8 warps,
// warp tile 64x64 (m16n8k16), ldmatrix frags, cp.async staging.
// Smem rows padded to 40 shorts (80B): row*20 mod 32 covers all banks.
// MODE 0: A = ps f32 (LDG+cvt in loop); out H1b = bf16(relu(D + c[seg])).
// MODE 1: A = H1b bf16 (cp.async); out g_part[bx] = per-row
//         sum_n relu(D + b2[n]) * W3[n] over this block's 256 cols.
// ====================================================================
#define ASTR 40                      // shorts per A smem row
#define ABUF 10240                   // 128*40*2 bytes per A stage
#define BBUF 20480                   // 256*40*2 bytes per B stage
#define SM_DYN (2 * ABUF + 2 * BBUF) // 61440

template <int MODE>
__global__ __launch_bounds__(256, 1)
void k_gemm(const float* __restrict__ Af,          // MODE 0 source (f32)
            const __nv_bfloat16* __restrict__ Ab,  // MODE 1 source (bf16)
            const __nv_bfloat16* __restrict__ WT,  // [n][k] bf16
            const int*   __restrict__ seg,         // MODE 0
            const float* __restrict__ b2,          // MODE 1
            const float* __restrict__ W3) {        // MODE 1
    extern __shared__ char sm[];
    __shared__ float s_red[4][128];
    __shared__ float s_b2[256], s_w3[256];

    const int tid  = threadIdx.x;
    const int wid  = tid >> 5, lane = tid & 31;
    const int g    = lane >> 2, tg = lane & 3;
    const int wm   = (wid >> 2) * 64;             // 0 / 64
    const int wn   = (wid & 3) * 64;              // 0..192
    const int row0 = blockIdx.y * 128;
    const int col0 = blockIdx.x * 256;
    const uint32_t sb = smem_u32(sm);

    if (MODE == 1) { s_b2[tid] = b2[col0 + tid]; s_w3[tid] = W3[col0 + tid]; }

    float acc[4][8][4];
#pragma unroll
    for (int mi = 0; mi < 4; mi++)
#pragma unroll
        for (int ni = 0; ni < 8; ni++)
#pragma unroll
            for (int q = 0; q < 4; q++) acc[mi][ni][q] = 0.f;

    // ldmatrix lane address components (fixed per thread)
    const int a_row = (lane & 7) + ((lane >> 3) & 1) * 8;
    const int a_kh  = (lane >> 4) & 1;
    const int b_n   = (lane & 7) + ((lane >> 4) & 1) * 8;
    const int b_kh  = (lane >> 3) & 1;

    float4 pa[4];                                  // MODE 0 A staging

#define CP_ISSUE(kt, buf) do { \
    const uint32_t bb = sb + 2 * ABUF + (buf) * BBUF; \
    _Pragma("unroll") \
    for (int j = 0; j < 4; j++) { \
        int c = tid + j * 256, n = c >> 2, part = c & 3; \
        CP16(bb + n * 80 + part * 16, \
             WT + (size_t)(col0 + n) * 512 + (kt) * 32 + part * 8); \
    } \
    if (MODE == 1) { \
        const uint32_t ab = sb + (buf) * ABUF; \
        _Pragma("unroll") \
        for (int j = 0; j < 2; j++) { \
            int c = tid + j * 256, r = c >> 2, part = c & 3; \
            CP16(ab + r * 80 + part * 16, \
                 Ab + (size_t)(row0 + r) * 512 + (kt) * 32 + part * 8); \
        } \
    } } while (0)

#define A_LDG(kt) do { \
    _Pragma("unroll") \
    for (int j = 0; j < 4; j++) { \
        int c = tid + j * 256, r = c >> 3, part = c & 7; \
        pa[j] = *(const float4*)(Af + (size_t)(row0 + r) * 512 + (kt) * 32 + part * 4); \
    } } while (0)

#define A_STS(buf) do { \
    const uint32_t ab = sb + (buf) * ABUF; \
    _Pragma("unroll") \
    for (int j = 0; j < 4; j++) { \
        int c = tid + j * 256, r = c >> 3, part = c & 7; \
        __nv_bfloat162 lo = __float22bfloat162_rn(make_float2(pa[j].x, pa[j].y)); \
        __nv_bfloat162 hi = __float22bfloat162_rn(make_float2(pa[j].z, pa[j].w)); \
        uint32_t ulo = *(uint32_t*)&lo, uhi = *(uint32_t*)&hi; \
        asm volatile("st.shared.v2.u32 [%0], {%1, %2};" \
            :: "r"(ab + r * 80 + part * 8), "r"(ulo), "r"(uhi)); \
    } } while (0)

    // prologue: stage 0
    CP_ISSUE(0, 0);
    CPCOMMIT();
    if (MODE == 0) { A_LDG(0); A_STS(0); }
    CPWAIT0();
    __syncthreads();

    for (int kt = 0; kt < 16; kt++) {
        const int buf = kt & 1;
        if (kt < 15) {
            CP_ISSUE(kt + 1, buf ^ 1);
            CPCOMMIT();
            if (MODE == 0) A_LDG(kt + 1);
        }
        const uint32_t ab = sb + buf * ABUF;
        const uint32_t bb = sb + 2 * ABUF + buf * BBUF;
#pragma unroll
        for (int ks = 0; ks < 2; ks++) {
            uint32_t af[4][4], bf[8][2];
#pragma unroll
            for (int mi = 0; mi < 4; mi++)
                LDSM4(af[mi], ab + (wm + mi * 16 + a_row) * 80 + ks * 32 + a_kh * 16);
#pragma unroll
            for (int p = 0; p < 4; p++) {
                uint32_t r4[4];
                LDSM4(r4, bb + (wn + p * 16 + b_n) * 80 + ks * 32 + b_kh * 16);
                bf[2 * p][0] = r4[0]; bf[2 * p][1] = r4[1];
                bf[2 * p + 1][0] = r4[2]; bf[2 * p + 1][1] = r4[3];
            }
#pragma unroll
            for (int mi = 0; mi < 4; mi++)
#pragma unroll
                for (int ni = 0; ni < 8; ni++)
                    MMA_BF16(acc[mi][ni], af[mi], bf[ni]);
        }
        if (kt < 15) {
            if (MODE == 0) A_STS(buf ^ 1);
            CPWAIT0();
            __syncthreads();
        }
    }

    // -------- epilogue --------
    if (MODE == 0) {
#pragma unroll
        for (int mi = 0; mi < 4; mi++) {
#pragma unroll
            for (int h = 0; h < 2; h++) {
                int r = row0 + wm + mi * 16 + g + h * 8;
                const float* crow = g_c + (size_t)__ldg(seg + r) * 512;
                __nv_bfloat16* orow = g_H1b + (size_t)r * 512;
#pragma unroll
                for (int ni = 0; ni < 8; ni++) {
                    int col = col0 + wn + ni * 8 + 2 * tg;
                    float x0 = fmaxf(acc[mi][ni][h * 2 + 0] + crow[col], 0.f);
                    float x1 = fmaxf(acc[mi][ni][h * 2 + 1] + crow[col + 1], 0.f);
                    __nv_bfloat162 o = __float22bfloat162_rn(make_float2(x0, x1));
                    *(__nv_bfloat162*)(orow + col) = o;
                }
            }
        }
    } else {
        float rp[4][2];
#pragma unroll
        for (int mi = 0; mi < 4; mi++) {
#pragma unroll
            for (int h = 0; h < 2; h++) {
                float s = 0.f;
#pragma unroll
                for (int ni = 0; ni < 8; ni++) {
                    int cl = wn + ni * 8 + 2 * tg;
                    s = fmaf(fmaxf(acc[mi][ni][h * 2 + 0] + s_b2[cl], 0.f), s_w3[cl], s);
                    s = fmaf(fmaxf(acc[mi][ni][h * 2 + 1] + s_b2[cl + 1], 0.f), s_w3[cl + 1], s);
                }
                s += __shfl_xor_sync(0xffffffffu, s, 1);
                s += __shfl_xor_sync(0xffffffffu, s, 2);
                rp[mi][h] = s;
            }
        }
        __syncthreads();
        if (tg == 0) {
#pragma unroll
            for (int mi = 0; mi < 4; mi++)
#pragma unroll
                for (int h = 0; h < 2; h++)
                    s_red[wid & 3][wm + mi * 16 + g + h * 8] = rp[mi][h];
        }
        __syncthreads();
        if (tid < 128) {
            float v = s_red[0][tid] + s_red[1][tid] + s_red[2][tid] + s_red[3][tid];
            g_part[(size_t)blockIdx.x * TT + row0 + tid] = v;
        }
    }
#undef CP_ISSUE
#undef A_LDG
#undef A_STS
}

// ====================================================================
// logits[t] = part0 + part1 + b3
// ====================================================================
__global__ void k_logit_red(const float* __restrict__ b3) {
    int t = blockIdx.x * 256 + threadIdx.x;
    g_logits[t] = g_part[t] + g_part[TT + t] + b3[0];
}

// ====================================================================
// K5: per-segment softmax + weighted pooling.  Grid (B, 4), 128 threads.
// ====================================================================
__global__ void k_seg_pool(const int* __restrict__ seg,
                           const float* __restrict__ ps) {
    __shared__ float sbuf[128];
    __shared__ float s_mx, s_dn;
    const int b   = blockIdx.x;
    const int tid = threadIdx.x;

    int lo = 0, hi = TT;
    while (lo < hi) { int mid = (lo + hi) >> 1; if (seg[mid] < b) lo = mid + 1; else hi = mid; }
    const int start = lo;
    hi = TT;
    while (lo < hi) { int mid = (lo + hi) >> 1; if (seg[mid] < b + 1) lo = mid + 1; else hi = mid; }
    const int end = lo;

    float m = -1e30f;
    for (int t = start + tid; t < end; t += 128) m = fmaxf(m, g_logits[t]);
    sbuf[tid] = m; __syncthreads();
    for (int s = 64; s > 0; s >>= 1) {
        if (tid < s) sbuf[tid] = fmaxf(sbuf[tid], sbuf[tid + s]);
        __syncthreads();
    }
    if (tid == 0) s_mx = sbuf[0];
    __syncthreads();
    const float mx = s_mx;

    float sm = 0.f;
    for (int t = start + tid; t < end; t += 128) sm += expf(g_logits[t] - mx);
    __syncthreads();
    sbuf[tid] = sm; __syncthreads();
    for (int s = 64; s > 0; s >>= 1) {
        if (tid < s) sbuf[tid] += sbuf[tid + s];
        __syncthreads();
    }
    if (tid == 0) s_dn = sbuf[0];
    __syncthreads();
    const float inv = (end > start) ? 1.f / s_dn : 0.f;

    const int col = blockIdx.y * 128 + tid;
    float acc = 0.f;
    for (int c0 = start; c0 < end; c0 += 128) {
        int nt = min(128, end - c0);
        __syncthreads();
        if (tid < nt) sbuf[tid] = expf(g_logits[c0 + tid] - mx);
        __syncthreads();
#pragma unroll 4
        for (int i = 0; i < nt; i++)
            acc = fmaf(sbuf[i], ps[(size_t)(c0 + i) * XX + col], acc);
    }
    g_pooled[(size_t)b * XX + col] = acc * inv;
}

// ====================================================================
// K6: out[b] = relu(pooled[b] @ Wf1 + bf1) @ Wf2 + bf2   (exact fp32)
// ====================================================================
__global__ void k_final(const float* __restrict__ Wf1,
                        const float* __restrict__ bf1,
                        const float* __restrict__ Wf2,
                        const float* __restrict__ bf2,
                        float* __restrict__ out) {
    __shared__ float p[512];
    __shared__ float hf[512];
    const int b = blockIdx.x;
    const int tid = threadIdx.x;

    p[tid] = g_pooled[b * XX + tid];
    __syncthreads();

    float acc = bf1[tid];
#pragma unroll 4
    for (int k = 0; k < 512; k++)
        acc = fmaf(p[k], Wf1[(size_t)k * 512 + tid], acc);
    hf[tid] = fmaxf(acc, 0.f);
    __syncthreads();

    float v0 = hf[tid] * Wf2[tid * 2 + 0];
    float v1 = hf[tid] * Wf2[tid * 2 + 1];
    __syncthreads();
    p[tid] = v0; __syncthreads();
    for (int s = 256; s > 0; s >>= 1) { if (tid < s) p[tid] += p[tid + s]; __syncthreads(); }
    if (tid == 0) out[b * 2 + 0] = p[0] + bf2[0];
    __syncthreads();
    p[tid] = v1; __syncthreads();
    for (int s = 256; s > 0; s >>= 1) { if (tid < s) p[tid] += p[tid + s]; __syncthreads(); }
    if (tid == 0) out[b * 2 + 1] = p[0] + bf2[1];
}

// ====================================================================
extern "C" void kernel_launch(void* const* d_in, const int* in_sizes, int n_in,
                              void* d_out, int out_size) {
    const float* ps  = (const float*)d_in[0];
    const float* io  = (const float*)d_in[1];
    const int*   seg = (const int*)  d_in[2];
    const float* W1  = (const float*)d_in[3];
    const float* b1  = (const float*)d_in[4];
    const float* W2  = (const float*)d_in[5];
    const float* b2  = (const float*)d_in[6];
    const float* W3  = (const float*)d_in[7];
    const float* b3  = (const float*)d_in[8];
    const float* Wf1 = (const float*)d_in[9];
    const float* bf1 = (const float*)d_in[10];
    const float* Wf2 = (const float*)d_in[11];
    const float* bf2 = (const float*)d_in[12];
    float* out = (float*)d_out;

    __nv_bfloat16 *H1b, *WT1b, *WT2b;
    cudaGetSymbolAddress((void**)&H1b,  g_H1b);
    cudaGetSymbolAddress((void**)&WT1b, g_WT1b);
    cudaGetSymbolAddress((void**)&WT2b, g_WT2b);

    cudaFuncSetAttribute(k_gemm<0>, cudaFuncAttributeMaxDynamicSharedMemorySize, SM_DYN);
    cudaFuncSetAttribute(k_gemm<1>, cudaFuncAttributeMaxDynamicSharedMemorySize, SM_DYN);

    dim3 tb(32, 8);
    k_wt<<<dim3(16, 16), tb>>>(W1, WT1b);   // rows 0..511 of W1
    k_wt<<<dim3(16, 16), tb>>>(W2, WT2b);
    k_compute_c<<<BB, 512>>>(io, W1, b1);

    // H1 = bf16(relu(ps @ W1a + c[seg]))
    k_gemm<0><<<dim3(2, TT / 128), 256, SM_DYN>>>(ps, nullptr, WT1b, seg, nullptr, nullptr);
    // logit partials = relu(H1 @ W2 + b2) . W3 per 256-col block
    k_gemm<1><<<dim3(2, TT / 128), 256, SM_DYN>>>(nullptr, H1b, WT2b, nullptr, b2, W3);

    k_logit_red<<<TT / 256, 256>>>(b3);
    k_seg_pool<<<dim3(BB, 4), 128>>>(seg, ps);
    k_final<<<BB, 512>>>(Wf1, bf1, Wf2, bf2, out);
}

// round 11
// speedup vs baseline: 3.6030x; 1.6428x over previous
#include <cuda_runtime.h>
#include <cuda_bf16.h>
#include <math.h>
#include <stdint.h>

#define TT 65536
#define BB 64
#define XX 512
#define HH 512
#define YY 2560

// -------- scratch (device globals; no allocation allowed) --------
__device__ float g_cpart[5][BB * HH];
__device__ float g_c[BB * HH];
__device__ __nv_bfloat16 g_H1b[(size_t)TT * HH];
__device__ __nv_bfloat16 g_WT1b[HH * HH];   // W1[:512] transposed [n][k], bf16
__device__ __nv_bfloat16 g_WT2b[HH * HH];   // W2 transposed [n][k], bf16
__device__ float g_part[4 * TT];
__device__ float g_logits[TT];
__device__ float g_pooled[BB * XX];

// ==================== PTX helpers ====================
__device__ __forceinline__ uint32_t smem_u32(const void* p) {
    uint32_t a;
    asm("{ .reg .u64 t; cvta.to.shared.u64 t, %1; cvt.u32.u64 %0, t; }"
        : "=r"(a) : "l"(p));
    return a;
}
#define CP16(dst, src) \
    asm volatile("cp.async.cg.shared.global [%0], [%1], 16;" :: "r"(dst), "l"(src))
#define CPCOMMIT() asm volatile("cp.async.commit_group;" ::: "memory")
#define CPWAIT0()  asm volatile("cp.async.wait_group 0;" ::: "memory")
#define CPWAIT1()  asm volatile("cp.async.wait_group 1;" ::: "memory")

#define LDSM4(r, addr) \
    asm volatile("ldmatrix.sync.aligned.m8n8.x4.shared.b16 {%0,%1,%2,%3}, [%4];" \
        : "=r"((r)[0]), "=r"((r)[1]), "=r"((r)[2]), "=r"((r)[3]) : "r"(addr))

#define MMA_BF16(d, a, b) \
    asm volatile("mma.sync.aligned.m16n8k16.row.col.f32.bf16.bf16.f32 " \
        "{%0,%1,%2,%3}, {%4,%5,%6,%7}, {%8,%9}, {%0,%1,%2,%3};" \
        : "+f"((d)[0]), "+f"((d)[1]), "+f"((d)[2]), "+f"((d)[3]) \
        : "r"((a)[0]), "r"((a)[1]), "r"((a)[2]), "r"((a)[3]), \
          "r"((b)[0]), "r"((b)[1]))

// ====================================================================
// K0: WT[n][k] = bf16(W[k][n])   (512x512 transpose + convert)
// ====================================================================
__global__ void k_wt(const float* __restrict__ W, __nv_bfloat16* __restrict__ WT) {
    __shared__ float t[32][33];
    int bx = blockIdx.x * 32, by = blockIdx.y * 32;
    int x = threadIdx.x, y = threadIdx.y;         // (32, 8)
#pragma unroll
    for (int i = 0; i < 32; i += 8)
        t[y + i][x] = W[(size_t)(by + y + i) * HH + bx + x];
    __syncthreads();
#pragma unroll
    for (int i = 0; i < 32; i += 8)
        WT[(size_t)(bx + y + i) * HH + by + x] = __float2bfloat16(t[x][y + i]);
}

// ====================================================================
// K1a: partial c over y-slice: cpart[s][b][h] = sum_{y in slice s} io*W1b
// grid (64, 5), 512 threads.  K1b: c = b1 + sum of 5 partials.
// ====================================================================
__global__ void k_compute_c_part(const float* __restrict__ io,
                                 const float* __restrict__ W1) {
    int b = blockIdx.x, s = blockIdx.y;
    int h = threadIdx.x;
    const float* e = io + b * YY + s * 512;
    const float* w = W1 + (size_t)(XX + s * 512) * HH + h;
    float a0 = 0.f, a1 = 0.f, a2 = 0.f, a3 = 0.f;
#pragma unroll 4
    for (int y = 0; y < 512; y += 4) {
        a0 = fmaf(e[y],     w[(size_t)y * HH],        a0);
        a1 = fmaf(e[y + 1], w[(size_t)(y + 1) * HH],  a1);
        a2 = fmaf(e[y + 2], w[(size_t)(y + 2) * HH],  a2);
        a3 = fmaf(e[y + 3], w[(size_t)(y + 3) * HH],  a3);
    }
    g_cpart[s][b * HH + h] = (a0 + a1) + (a2 + a3);
}
__global__ void k_compute_c_red(const float* __restrict__ b1) {
    int i = blockIdx.x * 512 + threadIdx.x;
    g_c[i] = b1[threadIdx.x] + g_cpart[0][i] + g_cpart[1][i]
           + g_cpart[2][i] + g_cpart[3][i] + g_cpart[4][i];
}

// ====================================================================
// bf16 mma.sync GEMM: block 128(M)x128(N), BK=32, 256 thr = 8 warps,
// warp tile 64x32, 3-stage cp.async pipeline (wait_group 1), 2 CTA/SM.
// Smem rows 40 shorts (80B): row*20 mod 32 covers all banks.
// MODE 0: A = ps f32 (LDG+cvt+STS); out H1b = bf16(relu(D + c[seg])).
// MODE 1: A = H1b bf16 (cp.async); out g_part[bx] = per-row
//         sum_n relu(D + b2[n]) * W3[n] over this block's 128 cols.
// ====================================================================
#define ABYT 10240                    // 128*40*2 per stage (A or B)
#define STG  20480                    // stage stride (A+B)
#define SM_DYN (3 * STG)              // 61440

template <int MODE>
__global__ __launch_bounds__(256, 2)
void k_gemm(const float* __restrict__ Af,          // MODE 0 source (f32)
            const __nv_bfloat16* __restrict__ Ab,  // MODE 1 source (bf16)
            const __nv_bfloat16* __restrict__ WT,  // [n][k] bf16
            const int*   __restrict__ seg,         // MODE 0
            const float* __restrict__ b2,          // MODE 1
            const float* __restrict__ W3) {        // MODE 1
    extern __shared__ char sm[];
    __shared__ float s_red[4][128];
    __shared__ float s_b2[128], s_w3[128];

    const int tid  = threadIdx.x;
    const int wid  = tid >> 5, lane = tid & 31;
    const int g    = lane >> 2, tg = lane & 3;
    const int wm   = (wid >> 2) * 64;             // 0 / 64
    const int wn   = (wid & 3) * 32;              // 0..96
    const int row0 = blockIdx.y * 128;
    const int col0 = blockIdx.x * 128;
    const uint32_t sb = smem_u32(sm);

    if (MODE == 1 && tid < 128) { s_b2[tid] = b2[col0 + tid]; s_w3[tid] = W3[col0 + tid]; }

    float acc[4][4][4];
#pragma unroll
    for (int mi = 0; mi < 4; mi++)
#pragma unroll
        for (int ni = 0; ni < 4; ni++)
#pragma unroll
            for (int q = 0; q < 4; q++) acc[mi][ni][q] = 0.f;

    // ldmatrix lane address components
    const int a_row = (lane & 7) + ((lane >> 3) & 1) * 8;
    const int a_kh  = (lane >> 4) & 1;
    const int b_n   = (lane & 7) + ((lane >> 4) & 1) * 8;
    const int b_kh  = (lane >> 3) & 1;

    float4 pa[4];                                  // MODE 0 A staging (one stage ahead)

#define CP_ISSUE(kt, st) do { \
    const uint32_t bbp = sb + (st) * STG + ABYT; \
    _Pragma("unroll") \
    for (int j = 0; j < 2; j++) { \
        int c = tid + j * 256, n = c >> 2, part = c & 3; \
        CP16(bbp + n * 80 + part * 16, \
             WT + (size_t)(col0 + n) * 512 + (kt) * 32 + part * 8); \
    } \
    if (MODE == 1) { \
        const uint32_t abp = sb + (st) * STG; \
        _Pragma("unroll") \
        for (int j = 0; j < 2; j++) { \
            int c = tid + j * 256, r = c >> 2, part = c & 3; \
            CP16(abp + r * 80 + part * 16, \
                 Ab + (size_t)(row0 + r) * 512 + (kt) * 32 + part * 8); \
        } \
    } } while (0)

#define A_LDG(kt) do { \
    _Pragma("unroll") \
    for (int j = 0; j < 4; j++) { \
        int c = tid + j * 256, r = c >> 3, part = c & 7; \
        pa[j] = *(const float4*)(Af + (size_t)(row0 + r) * 512 + (kt) * 32 + part * 4); \
    } } while (0)

#define A_STS(st) do { \
    const uint32_t abp = sb + (st) * STG; \
    _Pragma("unroll") \
    for (int j = 0; j < 4; j++) { \
        int c = tid + j * 256, r = c >> 3, part = c & 7; \
        __nv_bfloat162 lo = __float22bfloat162_rn(make_float2(pa[j].x, pa[j].y)); \
        __nv_bfloat162 hi = __float22bfloat162_rn(make_float2(pa[j].z, pa[j].w)); \
        uint32_t ulo = *(uint32_t*)&lo, uhi = *(uint32_t*)&hi; \
        asm volatile("st.shared.v2.u32 [%0], {%1, %2};" \
            :: "r"(abp + r * 80 + part * 8), "r"(ulo), "r"(uhi)); \
    } } while (0)

    // ---- prologue: stages 0 and 1 in flight ----
    CP_ISSUE(0, 0); CPCOMMIT();
    CP_ISSUE(1, 1); CPCOMMIT();
    if (MODE == 0) {
        A_LDG(0); A_STS(0);
        A_LDG(1); A_STS(1);
        A_LDG(2);                       // pa holds stage-2 data
    }

    for (int kt = 0; kt < 16; kt++) {
        const int buf = kt % 3;
        const int nxt = (kt + 2) % 3;
        if (kt >= 14) { CPWAIT0(); } else { CPWAIT1(); }   // stage kt arrived
        __syncthreads();
        if (kt < 14) {
            CP_ISSUE(kt + 2, nxt);
            CPCOMMIT();
            if (MODE == 0) {
                A_STS(nxt);             // pa = stage kt+2
                if (kt < 13) A_LDG(kt + 3);
            }
        }
        const uint32_t ab = sb + buf * STG;
        const uint32_t bb = ab + ABYT;
#pragma unroll
        for (int ks = 0; ks < 2; ks++) {
            uint32_t af[4][4], bf[4][2];
#pragma unroll
            for (int mi = 0; mi < 4; mi++)
                LDSM4(af[mi], ab + (wm + mi * 16 + a_row) * 80 + ks * 32 + a_kh * 16);
#pragma unroll
            for (int p = 0; p < 2; p++) {
                uint32_t r4[4];
                LDSM4(r4, bb + (wn + p * 16 + b_n) * 80 + ks * 32 + b_kh * 16);
                bf[2 * p][0] = r4[0]; bf[2 * p][1] = r4[1];
                bf[2 * p + 1][0] = r4[2]; bf[2 * p + 1][1] = r4[3];
            }
#pragma unroll
            for (int mi = 0; mi < 4; mi++)
#pragma unroll
                for (int ni = 0; ni < 4; ni++)
                    MMA_BF16(acc[mi][ni], af[mi], bf[ni]);
        }
    }

    // -------- epilogue --------
    if (MODE == 0) {
#pragma unroll
        for (int mi = 0; mi < 4; mi++) {
#pragma unroll
            for (int h = 0; h < 2; h++) {
                int r = row0 + wm + mi * 16 + g + h * 8;
                const float* crow = g_c + (size_t)__ldg(seg + r) * 512;
                __nv_bfloat16* orow = g_H1b + (size_t)r * 512;
#pragma unroll
                for (int ni = 0; ni < 4; ni++) {
                    int col = col0 + wn + ni * 8 + 2 * tg;
                    float x0 = fmaxf(acc[mi][ni][h * 2 + 0] + crow[col], 0.f);
                    float x1 = fmaxf(acc[mi][ni][h * 2 + 1] + crow[col + 1], 0.f);
                    __nv_bfloat162 o = __float22bfloat162_rn(make_float2(x0, x1));
                    *(__nv_bfloat162*)(orow + col) = o;
                }
            }
        }
    } else {
        float rp[4][2];
#pragma unroll
        for (int mi = 0; mi < 4; mi++) {
#pragma unroll
            for (int h = 0; h < 2; h++) {
                float s = 0.f;
#pragma unroll
                for (int ni = 0; ni < 4; ni++) {
                    int cl = wn + ni * 8 + 2 * tg;
                    s = fmaf(fmaxf(acc[mi][ni][h * 2 + 0] + s_b2[cl], 0.f), s_w3[cl], s);
                    s = fmaf(fmaxf(acc[mi][ni][h * 2 + 1] + s_b2[cl + 1], 0.f), s_w3[cl + 1], s);
                }
                s += __shfl_xor_sync(0xffffffffu, s, 1);
                s += __shfl_xor_sync(0xffffffffu, s, 2);
                rp[mi][h] = s;
            }
        }
        __syncthreads();
        if (tg == 0) {
#pragma unroll
            for (int mi = 0; mi < 4; mi++)
#pragma unroll
                for (int h = 0; h < 2; h++)
                    s_red[wid & 3][wm + mi * 16 + g + h * 8] = rp[mi][h];
        }
        __syncthreads();
        if (tid < 128) {
            float v = s_red[0][tid] + s_red[1][tid] + s_red[2][tid] + s_red[3][tid];
            g_part[(size_t)blockIdx.x * TT + row0 + tid] = v;
        }
    }
#undef CP_ISSUE
#undef A_LDG
#undef A_STS
}

// ====================================================================
// logits[t] = sum of 4 n-block partials + b3
// ====================================================================
__global__ void k_logit_red(const float* __restrict__ b3) {
    int t = blockIdx.x * 256 + threadIdx.x;
    g_logits[t] = ((g_part[t] + g_part[TT + t])
                + (g_part[2 * TT + t] + g_part[3 * TT + t])) + b3[0];
}

// ====================================================================
// K5: per-segment softmax + pooling.  64 blocks x 512 threads,
// thread = column (full coalesced 2KB row per token),
// 4 independent accumulator chains over tokens.
// ====================================================================
__global__ void k_seg_pool(const int* __restrict__ seg,
                           const float* __restrict__ ps) {
    __shared__ float sbuf[512];
    __shared__ float s_mx, s_dn;
    const int b   = blockIdx.x;
    const int tid = threadIdx.x;

    int lo = 0, hi = TT;
    while (lo < hi) { int mid = (lo + hi) >> 1; if (seg[mid] < b) lo = mid + 1; else hi = mid; }
    const int start = lo;
    hi = TT;
    while (lo < hi) { int mid = (lo + hi) >> 1; if (seg[mid] < b + 1) lo = mid + 1; else hi = mid; }
    const int end = lo;

    float m = -1e30f;
    for (int t = start + tid; t < end; t += 512) m = fmaxf(m, g_logits[t]);
    sbuf[tid] = m; __syncthreads();
    for (int s = 256; s > 0; s >>= 1) {
        if (tid < s) sbuf[tid] = fmaxf(sbuf[tid], sbuf[tid + s]);
        __syncthreads();
    }
    if (tid == 0) s_mx = sbuf[0];
    __syncthreads();
    const float mx = s_mx;

    float sm = 0.f;
    for (int t = start + tid; t < end; t += 512) sm += expf(g_logits[t] - mx);
    __syncthreads();
    sbuf[tid] = sm; __syncthreads();
    for (int s = 256; s > 0; s >>= 1) {
        if (tid < s) sbuf[tid] += sbuf[tid + s];
        __syncthreads();
    }
    if (tid == 0) s_dn = sbuf[0];
    __syncthreads();
    const float inv = (end > start) ? 1.f / s_dn : 0.f;

    float a0 = 0.f, a1 = 0.f, a2 = 0.f, a3 = 0.f;
    for (int c0 = start; c0 < end; c0 += 512) {
        int nt = min(512, end - c0);
        __syncthreads();
        if (tid < nt) sbuf[tid] = expf(g_logits[c0 + tid] - mx);
        __syncthreads();
        const float* prow = ps + (size_t)c0 * XX + tid;
        int i = 0;
        for (; i + 3 < nt; i += 4) {
            a0 = fmaf(sbuf[i],     prow[(size_t)(i)     * XX], a0);
            a1 = fmaf(sbuf[i + 1], prow[(size_t)(i + 1) * XX], a1);
            a2 = fmaf(sbuf[i + 2], prow[(size_t)(i + 2) * XX], a2);
            a3 = fmaf(sbuf[i + 3], prow[(size_t)(i + 3) * XX], a3);
        }
        for (; i < nt; i++)
            a0 = fmaf(sbuf[i], prow[(size_t)i * XX], a0);
    }
    g_pooled[(size_t)b * XX + tid] = ((a0 + a1) + (a2 + a3)) * inv;
}

// ====================================================================
// K6: out[b] = relu(pooled[b] @ Wf1 + bf1) @ Wf2 + bf2   (exact fp32)
// ====================================================================
__global__ void k_final(const float* __restrict__ Wf1,
                        const float* __restrict__ bf1,
                        const float* __restrict__ Wf2,
                        const float* __restrict__ bf2,
                        float* __restrict__ out) {
    __shared__ float p[512];
    __shared__ float hf[512];
    const int b = blockIdx.x;
    const int tid = threadIdx.x;

    p[tid] = g_pooled[b * XX + tid];
    __syncthreads();

    float acc = bf1[tid];
#pragma unroll 4
    for (int k = 0; k < 512; k++)
        acc = fmaf(p[k], Wf1[(size_t)k * 512 + tid], acc);
    hf[tid] = fmaxf(acc, 0.f);
    __syncthreads();

    float v0 = hf[tid] * Wf2[tid * 2 + 0];
    float v1 = hf[tid] * Wf2[tid * 2 + 1];
    __syncthreads();
    p[tid] = v0; __syncthreads();
    for (int s = 256; s > 0; s >>= 1) { if (tid < s) p[tid] += p[tid + s]; __syncthreads(); }
    if (tid == 0) out[b * 2 + 0] = p[0] + bf2[0];
    __syncthreads();
    p[tid] = v1; __syncthreads();
    for (int s = 256; s > 0; s >>= 1) { if (tid < s) p[tid] += p[tid + s]; __syncthreads(); }
    if (tid == 0) out[b * 2 + 1] = p[0] + bf2[1];
}

// ====================================================================
extern "C" void kernel_launch(void* const* d_in, const int* in_sizes, int n_in,
                              void* d_out, int out_size) {
    const float* ps  = (const float*)d_in[0];
    const float* io  = (const float*)d_in[1];
    const int*   seg = (const int*)  d_in[2];
    const float* W1  = (const float*)d_in[3];
    const float* b1  = (const float*)d_in[4];
    const float* W2  = (const float*)d_in[5];
    const float* b2  = (const float*)d_in[6];
    const float* W3  = (const float*)d_in[7];
    const float* b3  = (const float*)d_in[8];
    const float* Wf1 = (const float*)d_in[9];
    const float* bf1 = (const float*)d_in[10];
    const float* Wf2 = (const float*)d_in[11];
    const float* bf2 = (const float*)d_in[12];
    float* out = (float*)d_out;

    __nv_bfloat16 *H1b, *WT1b, *WT2b;
    cudaGetSymbolAddress((void**)&H1b,  g_H1b);
    cudaGetSymbolAddress((void**)&WT1b, g_WT1b);
    cudaGetSymbolAddress((void**)&WT2b, g_WT2b);

    cudaFuncSetAttribute(k_gemm<0>, cudaFuncAttributeMaxDynamicSharedMemorySize, SM_DYN);
    cudaFuncSetAttribute(k_gemm<1>, cudaFuncAttributeMaxDynamicSharedMemorySize, SM_DYN);

    dim3 tb(32, 8);
    k_wt<<<dim3(16, 16), tb>>>(W1, WT1b);   // rows 0..511 of W1
    k_wt<<<dim3(16, 16), tb>>>(W2, WT2b);
    k_compute_c_part<<<dim3(BB, 5), 512>>>(io, W1);
    k_compute_c_red<<<BB, 512>>>(b1);

    // H1 = bf16(relu(ps @ W1a + c[seg]))
    k_gemm<0><<<dim3(4, TT / 128), 256, SM_DYN>>>(ps, nullptr, WT1b, seg, nullptr, nullptr);
    // logit partials = relu(H1 @ W2 + b2) . W3 per 128-col block
    k_gemm<1><<<dim3(4, TT / 128), 256, SM_DYN>>>(nullptr, H1b, WT2b, nullptr, b2, W3);

    k_logit_red<<<TT / 256, 256>>>(b3);
    k_seg_pool<<<BB, 512>>>(seg, ps);
    k_final<<<BB, 512>>>(Wf1, bf1, Wf2, bf2, out);
}